// round 1
// baseline (speedup 1.0000x reference)
#include <cuda_runtime.h>
#include <math.h>

#define H 256
#define SEQ 256      // MAX_LENGTH
#define NL 4
#define VOC 50257
#define GRID 148
#define TPB 256
#define NWARP 8
#define TOTW (GRID*NWARP)

// -------- scratch (device globals: no allocation allowed) --------
__device__ __align__(16) float g_attn_logits[SEQ];
__device__ __align__(16) float g_part[32 * H];
__device__ __align__(16) float g_xbuf[2][H];
__device__ __align__(16) float2 g_red[GRID];
__device__ unsigned g_bar[16];   // zero-initialized; monotonic counters

// Monotonic-counter grid barrier: each launch each block arrives exactly once
// per index; target derived from old value, so no reset needed across graph
// replays. Requires all blocks co-resident (grid == 148 <= SM count).
__device__ __forceinline__ void gsync(int idx) {
    __syncthreads();
    if (threadIdx.x == 0) {
        __threadfence();
        unsigned old = atomicAdd(&g_bar[idx], 1u);
        unsigned target = (old / GRID + 1u) * GRID;
        while (*(volatile unsigned*)&g_bar[idx] < target) {
            __nanosleep(32);
        }
        __threadfence();
    }
    __syncthreads();
}

__device__ __forceinline__ float wredsum(float v) {
    #pragma unroll
    for (int o = 16; o; o >>= 1) v += __shfl_xor_sync(0xffffffffu, v, o);
    return v;
}

__global__ void __launch_bounds__(TPB, 1)
decoder_kernel(const int* __restrict__ token,
               const float* __restrict__ hidden,
               const float* __restrict__ enc,
               const float* __restrict__ emb,
               const float* __restrict__ attn_w,
               const float* __restrict__ attn_b,
               const float* __restrict__ comb_w,
               const float* __restrict__ comb_b,
               const float* __restrict__ gru_wih,
               const float* __restrict__ gru_whh,
               const float* __restrict__ gru_bih,
               const float* __restrict__ gru_bhh,
               const float* __restrict__ out_w,
               const float* __restrict__ out_b,
               float* __restrict__ out)
{
    const int tid  = threadIdx.x;
    const int bid  = blockIdx.x;
    const int wid  = tid >> 5;
    const int lane = tid & 31;
    const int gw   = bid * NWARP + wid;

    __shared__ float  s_a[H];
    __shared__ float  s_b[H];
    __shared__ float  s_red[TPB];
    __shared__ float4 s_x4[H / 4];
    __shared__ float  s_m[NWARP], s_s[NWARP];
    __shared__ float  s_lse;

    const int tok = token[0];  // int32 (or low word of int64 — same value)
    const float* erow = emb + (size_t)tok * H;

    // ---------------- Phase 1: attention logits (warp per output) ----------
    if (gw < SEQ) {
        const float* w = attn_w + (size_t)gw * (2 * H);
        float s = 0.f;
        #pragma unroll
        for (int t = 0; t < 16; t++) {
            int k = lane + 32 * t;
            float xin = (k < H) ? erow[k] : hidden[k - H];  // hidden[0]
            s = fmaf(xin, w[k], s);
        }
        s = wredsum(s);
        if (lane == 0) g_attn_logits[gw] = s + attn_b[gw];
    }
    gsync(0);

    // ---------- Phase 2+3: softmax (redundant per block) + applied partials
    if (bid < 32) {
        float v = g_attn_logits[tid];
        s_red[tid] = v; __syncthreads();
        #pragma unroll
        for (int o = 128; o; o >>= 1) {
            if (tid < o) s_red[tid] = fmaxf(s_red[tid], s_red[tid + o]);
            __syncthreads();
        }
        float m = s_red[0]; __syncthreads();
        float e = expf(v - m);
        s_red[tid] = e; __syncthreads();
        #pragma unroll
        for (int o = 128; o; o >>= 1) {
            if (tid < o) s_red[tid] += s_red[tid + o];
            __syncthreads();
        }
        float aw = e / s_red[0];
        s_a[tid] = aw;
        __syncthreads();
        if (bid == 0) out[VOC + NL * H + tid] = aw;   // attn_weights output

        // attn_applied partials: this block handles rows i in [bid*8, bid*8+8)
        float p = 0.f;
        #pragma unroll
        for (int r = 0; r < 8; r++) {
            int i = bid * 8 + r;
            p = fmaf(s_a[i], enc[(size_t)i * H + tid], p);
        }
        g_part[bid * H + tid] = p;
    }
    gsync(1);

    // ---------------- Phase 4: reduce partials + comb (relu) ---------------
    if (bid < 32) {
        float a = 0.f;
        #pragma unroll
        for (int b = 0; b < 32; b++) a += g_part[b * H + tid];
        s_b[tid] = a;                      // attn_applied
        __syncthreads();
        const float* w = comb_w + (size_t)gw * (2 * H);   // gw in 0..255
        float s = 0.f;
        #pragma unroll
        for (int t = 0; t < 16; t++) {
            int k = lane + 32 * t;
            float xin = (k < H) ? erow[k] : s_b[k - H];
            s = fmaf(xin, w[k], s);
        }
        s = wredsum(s);
        if (lane == 0) g_xbuf[0][gw] = fmaxf(s + comb_b[gw], 0.f);
    }
    gsync(2);

    // ---------------- GRU layers (warp per output j) -----------------------
    for (int l = 0; l < NL; l++) {
        if (bid < 32) {
            s_a[tid] = g_xbuf[l & 1][tid];     // x
            s_b[tid] = hidden[l * H + tid];    // h_in (input hidden)
            __syncthreads();
            const int j = gw;                  // 0..255
            const float* wih = gru_wih + (size_t)l * 3 * H * H;
            const float* whh = gru_whh + (size_t)l * 3 * H * H;
            float ir = 0.f, iz = 0.f, in_ = 0.f, hr = 0.f, hz = 0.f, hn = 0.f;
            #pragma unroll
            for (int t = 0; t < 8; t++) {
                int k = lane + 32 * t;
                float xv = s_a[k], hv = s_b[k];
                ir  = fmaf(xv, wih[(size_t)j * H + k],          ir);
                iz  = fmaf(xv, wih[(size_t)(H + j) * H + k],    iz);
                in_ = fmaf(xv, wih[(size_t)(2*H + j) * H + k],  in_);
                hr  = fmaf(hv, whh[(size_t)j * H + k],          hr);
                hz  = fmaf(hv, whh[(size_t)(H + j) * H + k],    hz);
                hn  = fmaf(hv, whh[(size_t)(2*H + j) * H + k],  hn);
            }
            ir = wredsum(ir); iz = wredsum(iz); in_ = wredsum(in_);
            hr = wredsum(hr); hz = wredsum(hz); hn  = wredsum(hn);
            if (lane == 0) {
                const float* bih = gru_bih + l * 3 * H;
                const float* bhh = gru_bhh + l * 3 * H;
                float r = 1.f / (1.f + expf(-((ir + bih[j])       + (hr + bhh[j]))));
                float z = 1.f / (1.f + expf(-((iz + bih[H + j])   + (hz + bhh[H + j]))));
                float n = tanhf((in_ + bih[2*H + j]) + r * (hn + bhh[2*H + j]));
                float hv = s_b[j];
                float hnew = (1.f - z) * n + z * hv;
                g_xbuf[(l + 1) & 1][j] = hnew;
                out[VOC + l * H + j] = hnew;   // hidden_new output
            }
        }
        gsync(3 + l);
    }

    // ---------------- Output projection + streaming logsumexp -------------
    {
        const float* x = g_xbuf[0];            // (3+1)&1 == 0
        if (tid < H / 4) s_x4[tid] = ((const float4*)x)[tid];
        __syncthreads();

        float m = -INFINITY, ssum = 0.f;       // meaningful on lane 0 only
        const int nblk4 = (VOC + 3) >> 2;      // groups of 4 contiguous rows
        for (int it = 0;; it++) {
            int blk = it * TOTW + gw;
            if (blk >= nblk4) break;
            int row0 = blk * 4;
            #pragma unroll
            for (int r = 0; r < 4; r++) {
                int row = row0 + r;
                if (row < VOC) {
                    const float4* wr = (const float4*)(out_w + (size_t)row * H);
                    float4 a0 = wr[lane], a1 = wr[lane + 32];
                    float4 x0 = s_x4[lane], x1 = s_x4[lane + 32];
                    float s = a0.x*x0.x + a0.y*x0.y + a0.z*x0.z + a0.w*x0.w
                            + a1.x*x1.x + a1.y*x1.y + a1.z*x1.z + a1.w*x1.w;
                    s = wredsum(s);
                    if (lane == 0) {
                        float v = s + out_b[row];
                        out[row] = v;
                        float m2 = fmaxf(m, v);
                        ssum = ssum * expf(m - m2) + expf(v - m2);
                        m = m2;
                    }
                }
            }
        }
        if (lane == 0) { s_m[wid] = m; s_s[wid] = ssum; }
        __syncthreads();
        if (tid == 0) {
            float M = -INFINITY;
            #pragma unroll
            for (int w2 = 0; w2 < NWARP; w2++) M = fmaxf(M, s_m[w2]);
            float S = 0.f;
            #pragma unroll
            for (int w2 = 0; w2 < NWARP; w2++) S += s_s[w2] * expf(s_m[w2] - M);
            g_red[bid] = make_float2(M, S);
        }
    }
    gsync(7);

    // ---------------- Finalize: lse (redundant per block) + subtract -------
    if (tid == 0) {
        float M = -INFINITY;
        for (int b = 0; b < GRID; b++) M = fmaxf(M, g_red[b].x);
        float S = 0.f;
        for (int b = 0; b < GRID; b++) {
            float2 p = g_red[b];
            S += p.y * expf(p.x - M);
        }
        s_lse = M + logf(S);
    }
    __syncthreads();
    float lse = s_lse;
    for (int i = bid * TPB + tid; i < VOC; i += GRID * TPB)
        out[i] -= lse;
}

extern "C" void kernel_launch(void* const* d_in, const int* in_sizes, int n_in,
                              void* d_out, int out_size) {
    decoder_kernel<<<GRID, TPB>>>(
        (const int*)d_in[0],    // token
        (const float*)d_in[1],  // hidden
        (const float*)d_in[2],  // encoder_outputs
        (const float*)d_in[3],  // emb
        (const float*)d_in[4],  // attn_w
        (const float*)d_in[5],  // attn_b
        (const float*)d_in[6],  // comb_w
        (const float*)d_in[7],  // comb_b
        (const float*)d_in[8],  // gru_wih
        (const float*)d_in[9],  // gru_whh
        (const float*)d_in[10], // gru_bih
        (const float*)d_in[11], // gru_bhh
        (const float*)d_in[12], // out_w
        (const float*)d_in[13], // out_b
        (float*)d_out);
}

// round 3
// speedup vs baseline: 1.2330x; 1.2330x over previous
#include <cuda_runtime.h>
#include <math.h>

#define H    256
#define H2   512
#define SEQ  256
#define NL   4
#define VOC  50257
#define GRID 148
#define TPB  256
#define NWARP 8
#define TOTW (GRID*NWARP)   // 1184
#define GEMV_ITERS 6        // 6*1184*8 = 56832 >= VOC

// ---------------- scratch (device globals; no allocation allowed) ----------
__device__ __align__(16) float  g_attn_logits[SEQ];
__device__ __align__(16) float  g_part[16 * H];
__device__ __align__(16) float  g_gh[NL * 3 * H];   // h@whh.T + bhh
__device__ __align__(16) float  g_xbuf[2][H];
__device__ __align__(16) float2 g_red[GRID];
__device__ __align__(16) unsigned g_flag[GRID];     // per-block monotonic flags
__device__ unsigned g_go;                           // master's release word

// ---------------- math helpers ---------------------------------------------
__device__ __forceinline__ float dot4f(float4 a, float4 b) {
    return fmaf(a.x, b.x, fmaf(a.y, b.y, fmaf(a.z, b.z, a.w * b.w)));
}
__device__ __forceinline__ float wredsum(float v) {
    #pragma unroll
    for (int o = 16; o; o >>= 1) v += __shfl_xor_sync(0xffffffffu, v, o);
    return v;
}
// packed 4-row warp reduce: lanes 0-7 end with full sum of d0, 8-15 d1,
// 16-23 d2, 24-31 d3 (value broadcast within each 8-lane group).
__device__ __forceinline__ float red4(float d0, float d1, float d2, float d3, int lane) {
    bool h16 = (lane & 16) != 0, h8 = (lane & 8) != 0;
    float k0 = (h16 ? d2 : d0) + __shfl_xor_sync(0xffffffffu, h16 ? d0 : d2, 16);
    float k1 = (h16 ? d3 : d1) + __shfl_xor_sync(0xffffffffu, h16 ? d1 : d3, 16);
    float v  = (h8 ? k1 : k0) + __shfl_xor_sync(0xffffffffu, h8 ? k0 : k1, 8);
    v += __shfl_xor_sync(0xffffffffu, v, 4);
    v += __shfl_xor_sync(0xffffffffu, v, 2);
    v += __shfl_xor_sync(0xffffffffu, v, 1);
    return v;
}
// f32x2 packed fma (FFMA2)
__device__ __forceinline__ unsigned long long pk2(float lo, float hi) {
    unsigned long long r;
    asm("mov.b64 %0,{%1,%2};" : "=l"(r) : "f"(lo), "f"(hi));
    return r;
}
__device__ __forceinline__ unsigned long long fma2(unsigned long long a,
                                                   unsigned long long b,
                                                   unsigned long long c) {
    unsigned long long d;
    asm("fma.rn.f32x2 %0,%1,%2,%3;" : "=l"(d) : "l"(a), "l"(b), "l"(c));
    return d;
}
__device__ __forceinline__ float upk_sum(unsigned long long v) {
    float lo, hi;
    asm("mov.b64 {%0,%1},%2;" : "=f"(lo), "=f"(hi) : "l"(v));
    return lo + hi;
}

// ---------------- flag barrier ---------------------------------------------
// Block 0 is master: polls all flags >= base+seq with 148 threads, then
// publishes go = gbase+seq. Others: store own flag, spin on go. Monotonic,
// no reset needed across graph replays (every block += 8 per launch).
__device__ __forceinline__ void gbar(int seq, int bid, int tid,
                                     unsigned base, unsigned gbase) {
    __syncthreads();
    if (bid == 0) {
        if (tid == 0) { __threadfence(); *(volatile unsigned*)&g_flag[0] = base + seq; }
        if (tid < GRID) {
            unsigned t = base + seq;
            while (*(volatile unsigned*)&g_flag[tid] < t) __nanosleep(40);
        }
        __syncthreads();
        if (tid == 0) { __threadfence(); *(volatile unsigned*)&g_go = gbase + seq; }
        __syncthreads();
    } else {
        if (tid == 0) {
            __threadfence(); *(volatile unsigned*)&g_flag[bid] = base + seq;
            unsigned t = gbase + seq;
            while (*(volatile unsigned*)&g_go < t) __nanosleep(40);
            __threadfence();
        }
        __syncthreads();
    }
}

__global__ void __launch_bounds__(TPB, 1)
decoder_kernel(const int* __restrict__ token,
               const float* __restrict__ hidden,
               const float* __restrict__ enc,
               const float* __restrict__ emb,
               const float* __restrict__ attn_w,
               const float* __restrict__ attn_b,
               const float* __restrict__ comb_w,
               const float* __restrict__ comb_b,
               const float* __restrict__ gru_wih,
               const float* __restrict__ gru_whh,
               const float* __restrict__ gru_bih,
               const float* __restrict__ gru_bhh,
               const float* __restrict__ out_w,
               const float* __restrict__ out_b,
               float* __restrict__ out)
{
    const int tid  = threadIdx.x;
    const int bid  = blockIdx.x;
    const int wid  = tid >> 5;
    const int lane = tid & 31;

    __shared__ __align__(16) float s_in[H2];
    __shared__ __align__(16) float s_x[H];
    __shared__ __align__(16) float s_aw[SEQ];
    __shared__ float s_red[NWARP];
    __shared__ float s_ms[2 * NWARP];
    __shared__ float s_bc[2];
    __shared__ unsigned s_u[2];

    if (tid == 0) {
        s_u[0] = *(volatile unsigned*)&g_flag[bid];  // all flags equal at entry
        s_u[1] = *(volatile unsigned*)&g_go;
    }
    __syncthreads();
    const unsigned base = s_u[0], gbase = s_u[1];

    // ====================== P0 (all blocks, no deps) ========================
    if (bid < 16) {
        // attention logits: 2 rows per warp (16 blocks x 8 warps x 2 = 256)
        const int tok = token[0];
        const float* erow = emb + (size_t)tok * H;
        s_in[tid]     = __ldg(erow + tid);
        s_in[H + tid] = __ldg(hidden + tid);      // hidden[0]
        __syncthreads();
        const float4* in4 = (const float4*)s_in;
        float4 xv[4];
        #pragma unroll
        for (int t = 0; t < 4; t++) xv[t] = in4[lane + 32 * t];
        const int r0 = (bid * NWARP + wid) * 2;
        const float4* w0 = (const float4*)(attn_w + (size_t)r0 * H2);
        const float4* w1 = (const float4*)(attn_w + (size_t)(r0 + 1) * H2);
        float d0 = 0.f, d1 = 0.f;
        #pragma unroll
        for (int t = 0; t < 4; t++) {
            d0 += dot4f(__ldg(w0 + lane + 32 * t), xv[t]);
            d1 += dot4f(__ldg(w1 + lane + 32 * t), xv[t]);
        }
        float v = red4(d0, d1, 0.f, 0.f, lane);
        if (lane == 0) __stcg(&g_attn_logits[r0],     v + __ldg(attn_b + r0));
        if (lane == 8) __stcg(&g_attn_logits[r0 + 1], v + __ldg(attn_b + r0 + 1));
    } else {
        // gh = h @ whh.T + bhh : warp per (layer, j); 1056 warps cover 1024
        int W = (bid - 16) * NWARP + wid;
        if (W < NL * H) {
            int l = W >> 8, j = W & 255;
            const float* whh = gru_whh + (size_t)l * 3 * H * H;
            const float4* h4 = (const float4*)(hidden + l * H);
            float4 ha = __ldg(h4 + lane), hb = __ldg(h4 + lane + 32);
            const float4* wr = (const float4*)(whh + (size_t)j * H);
            const float4* wz = (const float4*)(whh + (size_t)(H + j) * H);
            const float4* wn = (const float4*)(whh + (size_t)(2 * H + j) * H);
            float dr = dot4f(__ldg(wr + lane), ha) + dot4f(__ldg(wr + lane + 32), hb);
            float dz = dot4f(__ldg(wz + lane), ha) + dot4f(__ldg(wz + lane + 32), hb);
            float dn = dot4f(__ldg(wn + lane), ha) + dot4f(__ldg(wn + lane + 32), hb);
            float v = red4(dr, dz, dn, 0.f, lane);
            int part = lane >> 3;
            if ((lane & 7) == 0 && part < 3)
                __stcg(&g_gh[(l * 3 + part) * H + j],
                       v + __ldg(gru_bhh + (l * 3 + part) * H + j));
        }
    }

    // ====================== barrier bookkeeping split =======================
    if (bid < 16) {
        gbar(1, bid, tid, base, gbase);
        // ---- P1: softmax (redundant per block) + applied partials ----
        {
            float v = __ldcg(&g_attn_logits[tid]);
            float wm = v;
            #pragma unroll
            for (int o = 16; o; o >>= 1) wm = fmaxf(wm, __shfl_xor_sync(0xffffffffu, wm, o));
            if (lane == 0) s_red[wid] = wm;
            __syncthreads();
            if (tid == 0) {
                float m = s_red[0];
                #pragma unroll
                for (int w = 1; w < NWARP; w++) m = fmaxf(m, s_red[w]);
                s_bc[0] = m;
            }
            __syncthreads();
            float e = expf(v - s_bc[0]);
            float ws = e;
            #pragma unroll
            for (int o = 16; o; o >>= 1) ws += __shfl_xor_sync(0xffffffffu, ws, o);
            if (lane == 0) s_red[wid] = ws;
            __syncthreads();
            if (tid == 0) {
                float s = 0.f;
                #pragma unroll
                for (int w = 0; w < NWARP; w++) s += s_red[w];
                s_bc[1] = s;
            }
            __syncthreads();
            float aw = e / s_bc[1];
            s_aw[tid] = aw;
            if (bid == 0) out[VOC + NL * H + tid] = aw;   // attn_weights
            __syncthreads();
            // applied partial over 16 seq positions
            int ib = bid * 16;
            float a0 = 0.f, a1 = 0.f, a2 = 0.f, a3 = 0.f;
            #pragma unroll
            for (int ii = 0; ii < 16; ii += 4) {
                a0 = fmaf(s_aw[ib + ii + 0], __ldg(enc + (size_t)(ib + ii + 0) * H + tid), a0);
                a1 = fmaf(s_aw[ib + ii + 1], __ldg(enc + (size_t)(ib + ii + 1) * H + tid), a1);
                a2 = fmaf(s_aw[ib + ii + 2], __ldg(enc + (size_t)(ib + ii + 2) * H + tid), a2);
                a3 = fmaf(s_aw[ib + ii + 3], __ldg(enc + (size_t)(ib + ii + 3) * H + tid), a3);
            }
            __stcg(&g_part[bid * H + tid], (a0 + a1) + (a2 + a3));
        }
        gbar(2, bid, tid, base, gbase);
    } else if (bid < 32) {
        // arrive for seq1+seq2 at once, wait for applied partials
        __syncthreads();
        if (tid == 0) {
            __threadfence(); *(volatile unsigned*)&g_flag[bid] = base + 2u;
            unsigned t = gbase + 2u;
            while (*(volatile unsigned*)&g_go < t) __nanosleep(64);
            __threadfence();
        }
        __syncthreads();
    } else {
        // arrive for seq1..7 at once, wait for x-ready (seq7)
        __syncthreads();
        if (tid == 0) {
            __threadfence(); *(volatile unsigned*)&g_flag[bid] = base + 7u;
            unsigned t = gbase + 7u;
            while (*(volatile unsigned*)&g_go < t) __nanosleep(128);
            __threadfence();
        }
        __syncthreads();
    }

    // ====================== P2 + GRU: chain blocks 0..31 ====================
    if (bid < 32) {
        // comb: warp per row j (32 blocks x 8 warps = 256)
        {
            const int tok = token[0];
            const float* erow = emb + (size_t)tok * H;
            s_in[tid] = __ldg(erow + tid);
            float ap = 0.f;
            #pragma unroll
            for (int c = 0; c < 16; c++) ap += __ldcg(&g_part[c * H + tid]);
            s_in[H + tid] = ap;
            __syncthreads();
            const float4* in4 = (const float4*)s_in;
            float4 xv[4];
            #pragma unroll
            for (int t = 0; t < 4; t++) xv[t] = in4[lane + 32 * t];
            const int j = bid * NWARP + wid;
            const float4* w4 = (const float4*)(comb_w + (size_t)j * H2);
            float d = 0.f;
            #pragma unroll
            for (int t = 0; t < 4; t++) d += dot4f(__ldg(w4 + lane + 32 * t), xv[t]);
            d = wredsum(d);
            if (lane == 0)
                __stcg(&g_xbuf[0][j], fmaxf(d + __ldg(comb_b + j), 0.f));
        }
        gbar(3, bid, tid, base, gbase);

        // GRU layers: warp per j, 3 gate rows each
        for (int l = 0; l < NL; l++) {
            s_x[tid] = __ldcg(&g_xbuf[l & 1][tid]);
            __syncthreads();
            const int j = bid * NWARP + wid;
            const float* wih = gru_wih + (size_t)l * 3 * H * H;
            float p_ghr = __ldcg(&g_gh[(l * 3 + 0) * H + j]);
            float p_ghz = __ldcg(&g_gh[(l * 3 + 1) * H + j]);
            float p_ghn = __ldcg(&g_gh[(l * 3 + 2) * H + j]);
            float p_br  = __ldg(gru_bih + (l * 3 + 0) * H + j);
            float p_bz  = __ldg(gru_bih + (l * 3 + 1) * H + j);
            float p_bn  = __ldg(gru_bih + (l * 3 + 2) * H + j);
            float p_h   = __ldg(hidden + l * H + j);
            const float4* x4 = (const float4*)s_x;
            float4 xa = x4[lane], xb = x4[lane + 32];
            const float4* wr = (const float4*)(wih + (size_t)j * H);
            const float4* wz = (const float4*)(wih + (size_t)(H + j) * H);
            const float4* wn = (const float4*)(wih + (size_t)(2 * H + j) * H);
            float dr = dot4f(__ldg(wr + lane), xa) + dot4f(__ldg(wr + lane + 32), xb);
            float dz = dot4f(__ldg(wz + lane), xa) + dot4f(__ldg(wz + lane + 32), xb);
            float dn = dot4f(__ldg(wn + lane), xa) + dot4f(__ldg(wn + lane + 32), xb);
            float v = red4(dr, dz, dn, 0.f, lane);
            float rs = __shfl_sync(0xffffffffu, v, 0);
            float zs = __shfl_sync(0xffffffffu, v, 8);
            float ns = __shfl_sync(0xffffffffu, v, 16);
            if (lane == 0) {
                float r = 1.f / (1.f + expf(-((rs + p_br) + p_ghr)));
                float z = 1.f / (1.f + expf(-((zs + p_bz) + p_ghz)));
                float n = tanhf((ns + p_bn) + r * p_ghn);
                float hnew = (1.f - z) * n + z * p_h;
                __stcg(&g_xbuf[(l + 1) & 1][j], hnew);
                out[VOC + l * H + j] = hnew;           // hidden_new
            }
            gbar(4 + l, bid, tid, base, gbase);        // seq 4,5,6,7
        }
    }

    // ====================== GEMV + streaming logsumexp (all) ================
    s_x[tid] = __ldcg(&g_xbuf[0][tid]);   // NL even -> final x in buf 0
    __syncthreads();
    {
        const float4* x4 = (const float4*)s_x;
        float4 xa = x4[lane], xb = x4[lane + 32];
        unsigned long long xp0 = pk2(xa.x, xa.y), xp1 = pk2(xa.z, xa.w);
        unsigned long long xp2 = pk2(xb.x, xb.y), xp3 = pk2(xb.z, xb.w);
        const int gwid = bid * NWARP + wid;
        const int rown = lane >> 2;
        const bool own = (lane & 3) == 0;
        float mM = -1e30f, sS = 0.f;
        #pragma unroll 1
        for (int it = 0; it < GEMV_ITERS; it++) {
            int r0 = (it * TOTW + gwid) * 8;
            int myrow = r0 + rown;
            float bias = (own && myrow < VOC) ? __ldg(out_b + myrow) : 0.f;
            float d[8];
            #pragma unroll
            for (int i = 0; i < 8; i++) {
                int row = r0 + i;
                float s = 0.f;
                if (row < VOC) {
                    const float4* wr = (const float4*)(out_w + (size_t)row * H);
                    float4 a0 = __ldg(wr + lane), a1 = __ldg(wr + lane + 32);
                    unsigned long long acc =
                        fma2(pk2(a0.x, a0.y), xp0,
                        fma2(pk2(a0.z, a0.w), xp1,
                        fma2(pk2(a1.x, a1.y), xp2,
                        fma2(pk2(a1.z, a1.w), xp3, 0ull))));
                    s = upk_sum(acc);
                }
                d[i] = s;
            }
            bool h16 = (lane & 16) != 0, h8 = (lane & 8) != 0, h4b = (lane & 4) != 0;
            float k0 = (h16 ? d[4] : d[0]) + __shfl_xor_sync(0xffffffffu, h16 ? d[0] : d[4], 16);
            float k1 = (h16 ? d[5] : d[1]) + __shfl_xor_sync(0xffffffffu, h16 ? d[1] : d[5], 16);
            float k2 = (h16 ? d[6] : d[2]) + __shfl_xor_sync(0xffffffffu, h16 ? d[2] : d[6], 16);
            float k3 = (h16 ? d[7] : d[3]) + __shfl_xor_sync(0xffffffffu, h16 ? d[3] : d[7], 16);
            float m0 = (h8 ? k2 : k0) + __shfl_xor_sync(0xffffffffu, h8 ? k0 : k2, 8);
            float m1 = (h8 ? k3 : k1) + __shfl_xor_sync(0xffffffffu, h8 ? k1 : k3, 8);
            float v  = (h4b ? m1 : m0) + __shfl_xor_sync(0xffffffffu, h4b ? m0 : m1, 4);
            v += __shfl_xor_sync(0xffffffffu, v, 2);
            v += __shfl_xor_sync(0xffffffffu, v, 1);
            if (own && myrow < VOC) {
                v += bias;
                out[myrow] = v;
                float m2 = fmaxf(mM, v);
                sS = sS * expf(mM - m2) + expf(v - m2);
                mM = m2;
            }
        }
        #pragma unroll
        for (int o = 16; o; o >>= 1) {
            float om = __shfl_xor_sync(0xffffffffu, mM, o);
            float os = __shfl_xor_sync(0xffffffffu, sS, o);
            float m2 = fmaxf(mM, om);
            sS = sS * expf(mM - m2) + os * expf(om - m2);
            mM = m2;
        }
        if (lane == 0) { s_ms[wid] = mM; s_ms[NWARP + wid] = sS; }
        __syncthreads();
        if (tid == 0) {
            float M = s_ms[0], S = s_ms[NWARP];
            #pragma unroll
            for (int w = 1; w < NWARP; w++) {
                float m2 = fmaxf(M, s_ms[w]);
                S = S * expf(M - m2) + s_ms[NWARP + w] * expf(s_ms[w] - m2);
                M = m2;
            }
            __stcg(&g_red[bid], make_float2(M, S));
        }
    }
    gbar(8, bid, tid, base, gbase);

    // ====================== finalize lse (redundant) + subtract =============
    if (wid == 0) {
        float M = -1e30f, S = 0.f;
        for (int e = lane; e < GRID; e += 32) {
            float2 p = __ldcg(&g_red[e]);
            float m2 = fmaxf(M, p.x);
            S = S * expf(M - m2) + p.y * expf(p.x - m2);
            M = m2;
        }
        #pragma unroll
        for (int o = 16; o; o >>= 1) {
            float om = __shfl_xor_sync(0xffffffffu, M, o);
            float os = __shfl_xor_sync(0xffffffffu, S, o);
            float m2 = fmaxf(M, om);
            S = S * expf(M - m2) + os * expf(om - m2);
            M = m2;
        }
        if (lane == 0) s_bc[0] = M + logf(S);
    }
    __syncthreads();
    float lse = s_bc[0];
    for (int i = bid * TPB + tid; i < VOC; i += GRID * TPB)
        out[i] = __ldcg(out + i) - lse;
}

extern "C" void kernel_launch(void* const* d_in, const int* in_sizes, int n_in,
                              void* d_out, int out_size) {
    decoder_kernel<<<GRID, TPB>>>(
        (const int*)d_in[0],    // token
        (const float*)d_in[1],  // hidden
        (const float*)d_in[2],  // encoder_outputs
        (const float*)d_in[3],  // emb
        (const float*)d_in[4],  // attn_w
        (const float*)d_in[5],  // attn_b
        (const float*)d_in[6],  // comb_w
        (const float*)d_in[7],  // comb_b
        (const float*)d_in[8],  // gru_wih
        (const float*)d_in[9],  // gru_whh
        (const float*)d_in[10], // gru_bih
        (const float*)d_in[11], // gru_bhh
        (const float*)d_in[12], // out_w
        (const float*)d_in[13], // out_b
        (float*)d_out);
}